// round 15
// baseline (speedup 1.0000x reference)
#include <cuda_runtime.h>
#include <cuda_fp16.h>

#define BSZ   2
#define NTOK  2048
#define DIM   1024
#define NHEAD 16
#define HDIM  64

// fp16 scratch. Everything stored hi-only downstream of the projections;
// x keeps hi+lo (the lo pass protects Q_hi accuracy inside gemm0).
__device__ __half g_xh[4096 * 1024],  g_xl[4096 * 1024];
__device__ __half g_wh[4096 * 1024];
__device__ __half g_qkvh[3 * 4096 * 1024];
__device__ __half g_oh[4096 * 1024];

// Q pre-scale: 1/sqrt(64) * log2(e)  (softmax runs in log2 domain)
#define QSCALE 0.18033688011112042f

// ---------------- primitives ----------------------------------------------
__device__ __forceinline__ void split2v(float x, float y, __half2& h, __half2& l) {
    h = __floats2half2_rn(x, y);
    float2 f = __half22float2(h);
    l = __floats2half2_rn(x - f.x, y - f.y);
}
__device__ __forceinline__ float ex2(float x) {
    float r;
    asm("ex2.approx.f32 %0, %1;" : "=f"(r) : "f"(x));
    return r;
}
__device__ __forceinline__ void mma16(float* c, const unsigned* a,
                                      unsigned b0, unsigned b1) {
    asm volatile(
        "mma.sync.aligned.m16n8k16.row.col.f32.f16.f16.f32 "
        "{%0,%1,%2,%3}, {%4,%5,%6,%7}, {%8,%9}, {%0,%1,%2,%3};"
        : "+f"(c[0]), "+f"(c[1]), "+f"(c[2]), "+f"(c[3])
        : "r"(a[0]), "r"(a[1]), "r"(a[2]), "r"(a[3]), "r"(b0), "r"(b1));
}
__device__ __forceinline__ void ldsm4(unsigned* r, unsigned addr) {
    asm volatile("ldmatrix.sync.aligned.m8n8.x4.shared.b16 {%0,%1,%2,%3}, [%4];"
        : "=r"(r[0]), "=r"(r[1]), "=r"(r[2]), "=r"(r[3]) : "r"(addr));
}
__device__ __forceinline__ void ldsm4t(unsigned* r, unsigned addr) {
    asm volatile("ldmatrix.sync.aligned.m8n8.x4.trans.shared.b16 {%0,%1,%2,%3}, [%4];"
        : "=r"(r[0]), "=r"(r[1]), "=r"(r[2]), "=r"(r[3]) : "r"(addr));
}
__device__ __forceinline__ void cpa(unsigned dst, const void* src) {
    asm volatile("cp.async.cg.shared.global [%0], [%1], 16;" :: "r"(dst), "l"(src));
}
__device__ __forceinline__ void cpcommit() { asm volatile("cp.async.commit_group;"); }
template <int N> __device__ __forceinline__ void cpwait() {
    asm volatile("cp.async.wait_group %0;" :: "n"(N));
}

// ---------------- pre-split pass (x and W fused) -----------------------------
__global__ void presplit(const float* __restrict__ x,
                         const float* __restrict__ W0, const float* __restrict__ W1,
                         const float* __restrict__ W2, const float* __restrict__ W3,
                         const float* __restrict__ W4, const float* __restrict__ W5,
                         const float* __restrict__ W6,
                         __half* __restrict__ xh, __half* __restrict__ xl,
                         __half* __restrict__ wh) {
    if (blockIdx.x < 4096) {
        int id = blockIdx.x * 256 + threadIdx.x;
        float4 v = reinterpret_cast<const float4*>(x)[id];
        __half2 h0, l0, h1, l1;
        split2v(v.x, v.y, h0, l0);
        split2v(v.z, v.w, h1, l1);
        reinterpret_cast<__half2*>(xh)[id * 2]     = h0;
        reinterpret_cast<__half2*>(xh)[id * 2 + 1] = h1;
        reinterpret_cast<__half2*>(xl)[id * 2]     = l0;
        reinterpret_cast<__half2*>(xl)[id * 2 + 1] = l1;
    } else {
        int id  = (blockIdx.x - 4096) * 256 + threadIdx.x;
        int row = id >> 8;
        int q   = id & 255;
        const float* src;
        int rr;
        if (row < 3072) {
            int t = row >> 9;
            src = (t == 0) ? W0 : (t == 1) ? W1 : (t == 2) ? W2
                : (t == 3) ? W3 : (t == 4) ? W4 : W5;
            rr = row & 511;
        } else {
            src = W6; rr = row - 3072;
        }
        float4 v = reinterpret_cast<const float4*>(src + (size_t)rr * DIM)[q];
        __half2 h0 = __floats2half2_rn(v.x, v.y);
        __half2 h1 = __floats2half2_rn(v.z, v.w);
        reinterpret_cast<__half2*>(wh)[id * 2]     = h0;
        reinterpret_cast<__half2*>(wh)[id * 2 + 1] = h1;
    }
}

// ---------------------------------------------------------------------------
// fp16x2 GEMM: C = (A_hi [+ A_lo]) * W_hi^T.
// 4 warps/CTA, warp tile 64x64 (2x2 grid) -> 16 ldsm4 per 64 HMMA per stage
// (1.5x fewer LDSM per MMA than 64x32). 3-stage cp.async pipeline, one
// __syncthreads per k-stage. A_lo pass only for Q column tiles in MODE 0.
// ---------------------------------------------------------------------------
#define GSTR 40
#define GSTAGE 30720
#define GEMM_SMEM (3 * GSTAGE)

template <int MODE>
__global__ void __launch_bounds__(128, 2)
gemm_hl(const __half* __restrict__ Ah, const __half* __restrict__ Al,
        const __half* __restrict__ Wh,
        __half* __restrict__ Ch,
        float* __restrict__ Cf) {
    extern __shared__ __half smx[];
    const unsigned sbase = (unsigned)__cvta_generic_to_shared(smx);

    const int tid  = threadIdx.x;
    const int lane = tid & 31;
    const int wid  = tid >> 5;          // 0..3
    const int wm   = (wid & 1) * 64;
    const int wn   = (wid >> 1) * 64;
    const int row0 = blockIdx.y * 128;
    const int col0 = blockIdx.x * 128;
    const int wrow0 = (MODE == 0) ? col0 : (col0 + 3072);
    const bool doLo = (MODE == 0) && (blockIdx.x < 8);   // Q tiles only

    const int crow = tid >> 2;          // 0..31
    const int ckc  = tid & 3;

    auto issue = [&](int s) {
        const unsigned stb = sbase + (unsigned)((s % 3) * GSTAGE);
        const int k0 = s * 32;
        #pragma unroll
        for (int i = 0; i < 4; i++) {
            int row = crow + i * 32;
            unsigned doff = row * 80 + ckc * 16;
            size_t soffA = (size_t)(row0 + row) * DIM + k0 + ckc * 8;
            size_t soffB = (size_t)(wrow0 + row) * DIM + k0 + ckc * 8;
            cpa(stb + doff,         Ah + soffA);
            if (doLo) cpa(stb + 10240 + doff, Al + soffA);
            cpa(stb + 20480 + doff, Wh + soffB);
        }
        cpcommit();
    };

    float acc[4][8][4] = {};

    issue(0);
    issue(1);

    #pragma unroll 1
    for (int s = 0; s < 32; s++) {
        if (s < 31) cpwait<1>(); else cpwait<0>();
        __syncthreads();
        if (s + 2 < 32) issue(s + 2);

        const unsigned stb = sbase + (unsigned)((s % 3) * GSTAGE);
        #pragma unroll
        for (int ks = 0; ks < 2; ks++) {
            unsigned bh[4][4];
            #pragma unroll
            for (int np = 0; np < 4; np++) {
                unsigned off = stb + 20480 +
                    ((wn + np * 16 + (lane >> 4) * 8 + (lane & 7)) * GSTR
                     + ks * 16 + ((lane >> 3) & 1) * 8) * 2;
                ldsm4(bh[np], off);
            }
            #pragma unroll
            for (int mi = 0; mi < 4; mi++) {
                unsigned ah[4], al[4];
                unsigned off = stb + ((wm + mi * 16 + (lane & 15)) * GSTR
                                      + ks * 16 + (lane >> 4) * 8) * 2;
                ldsm4(ah, off);
                if (doLo) ldsm4(al, off + 10240);
                #pragma unroll
                for (int ni = 0; ni < 8; ni++) {
                    unsigned b0 = bh[ni >> 1][(ni & 1) * 2];
                    unsigned b1 = bh[ni >> 1][(ni & 1) * 2 + 1];
                    mma16(acc[mi][ni], ah, b0, b1);
                    if (doLo) mma16(acc[mi][ni], al, b0, b1);
                }
            }
        }
    }

    // epilogue
    #pragma unroll
    for (int mi = 0; mi < 4; mi++) {
        int r = row0 + wm + mi * 16 + (lane >> 2);
        #pragma unroll
        for (int ni = 0; ni < 8; ni++) {
            int c = col0 + wn + ni * 8 + 2 * (lane & 3);
            if (MODE == 0) {
                int m = c >> 10, j = c & 1023;
                float qs = (m == 0) ? QSCALE : 1.0f;   // Q pre-scale
                __half2 h0 = __floats2half2_rn(acc[mi][ni][0] * qs,
                                               acc[mi][ni][1] * qs);
                __half2 h1 = __floats2half2_rn(acc[mi][ni][2] * qs,
                                               acc[mi][ni][3] * qs);
                int hh = j >> 6, e = j & 63;
                int b = r >> 11, n = r & 2047;
                size_t idx = ((((size_t)(m * 2 + b) * 16 + hh) * NTOK) + n) * HDIM + e;
                *reinterpret_cast<__half2*>(&Ch[idx])            = h0;
                *reinterpret_cast<__half2*>(&Ch[idx + 8 * HDIM]) = h1;
            } else {
                float2 v0 = make_float2(acc[mi][ni][0], acc[mi][ni][1]);
                float2 v1 = make_float2(acc[mi][ni][2], acc[mi][ni][3]);
                *reinterpret_cast<float2*>(&Cf[(size_t)r * DIM + c])       = v0;
                *reinterpret_cast<float2*>(&Cf[(size_t)(r + 8) * DIM + c]) = v1;
            }
        }
    }
}

// ---------------------------------------------------------------------------
// fp16 flash attention (hi-only operands), 2-phase load-balanced, 3-buffer
// single-barrier pipeline. Fully-masked diag ktiles skipped per-warp.
// smem: Q_hi (18432) | 3 x KV buffer (K 9216 + V 9216)
// ---------------------------------------------------------------------------
#define AQH   0u
#define ABUF  18432u
#define ABUFSZ 18432u
#define AKH   0u
#define AVH   9216u
#define ATTN_SMEM 73728
#define KSTR  72

__global__ void __launch_bounds__(256, 2)
attn_hl(const __half* __restrict__ QKVh, __half* __restrict__ Oh) {
    extern __shared__ __half sma[];
    const unsigned sbase = (unsigned)__cvta_generic_to_shared(sma);

    const int qt  = blockIdx.x;     // 0..15 (128-row q tiles)
    const int b   = blockIdx.z;
    const int tid  = threadIdx.x;
    const int lane = tid & 31;
    const int w    = tid >> 5;
    const int quad = lane & 3;
    const int gpr  = lane >> 2;

    const int gq0 = qt * 128 + w * 16 + gpr;
    const int gq1 = gq0 + 8;

    #pragma unroll 1
    for (int ph = 0; ph < 2; ph++) {
        const int h = blockIdx.y + ph * 8;
        const bool causal = (ph == 0);

        const size_t hb = ((size_t)b * 16 + h) * NTOK * HDIM;
        const __half* Qgh = QKVh + hb;
        const __half* Kgh = QKVh + 2 * 2048 * 1024 + hb;
        const __half* Vgh = QKVh + 4 * 2048 * 1024 + hb;

        const int kt0 = causal ? 0 : (2 * qt);
        const int kt1 = causal ? (2 * qt + 1) : (NTOK / 64 - 1);

        auto issue_kv = [&](int kt, int buf) {
            #pragma unroll
            for (int i = 0; i < 2; i++) {
                int c = tid + i * 256;
                int key = c >> 3, ec = c & 7;
                size_t soff = (size_t)(kt * 64 + key) * HDIM + ec * 8;
                unsigned doff = sbase + ABUF + buf * ABUFSZ + key * 144 + ec * 16;
                cpa(doff + AKH, Kgh + soff);
                cpa(doff + AVH, Vgh + soff);
            }
            cpcommit();
        };

        // barrier: previous phase (or nothing) fully done with smem
        __syncthreads();

        // prologue: Q tile (128 rows x 8 chunks = 1024 chunks) + KV tile kt0
        // in group 0; KV kt0+1 in group 1
        {
            #pragma unroll
            for (int i = 0; i < 4; i++) {
                int c = tid + i * 256;                // 0..1023
                int row = c >> 3, ec = c & 7;
                size_t soff = (size_t)(qt * 128 + row) * HDIM + ec * 8;
                cpa(sbase + AQH + row * 144 + ec * 16, Qgh + soff);
            }
            #pragma unroll
            for (int i = 0; i < 2; i++) {
                int c = tid + i * 256;
                int key = c >> 3, ec = c & 7;
                size_t soff = (size_t)(kt0 * 64 + key) * HDIM + ec * 8;
                unsigned doff = sbase + ABUF + 0 * ABUFSZ + key * 144 + ec * 16;
                cpa(doff + AKH, Kgh + soff);
                cpa(doff + AVH, Vgh + soff);
            }
            cpcommit();
        }
        if (kt0 + 1 <= kt1) issue_kv(kt0 + 1, 1);

        float o[8][4] = {};
        float m0 = -1e30f, m1 = -1e30f, l0 = 0.f, l1 = 0.f;

        #pragma unroll 1
        for (int kt = kt0; kt <= kt1; kt++) {
            const int i3 = (kt - kt0) % 3;
            if (kt < kt1) cpwait<1>(); else cpwait<0>();
            __syncthreads();
            if (kt + 2 <= kt1) issue_kv(kt + 2, (i3 + 2) % 3);

            // warp-granular skip of fully-masked diag ktile (exact no-op)
            const bool skipw = causal ? (kt == 2 * qt + 1 && w < 4)
                                      : (kt == 2 * qt && w >= 4);
            if (skipw) continue;

            const unsigned kvb = sbase + ABUF + i3 * ABUFSZ;

            // S = Q_hi K_hi^T (log2 domain)
            float sc[8][4] = {};
            #pragma unroll
            for (int ks = 0; ks < 4; ks++) {
                unsigned qh[4];
                unsigned qoff = ((w * 16 + (lane & 15)) * KSTR
                                 + ks * 16 + (lane >> 4) * 8) * 2;
                ldsm4(qh, sbase + AQH + qoff);
                #pragma unroll
                for (int np = 0; np < 4; np++) {
                    unsigned kh[4];
                    unsigned koff = ((np * 16 + (lane >> 4) * 8 + (lane & 7)) * KSTR
                                     + ks * 16 + ((lane >> 3) & 1) * 8) * 2;
                    ldsm4(kh, kvb + AKH + koff);
                    mma16(sc[2 * np],     qh, kh[0], kh[1]);
                    mma16(sc[2 * np + 1], qh, kh[2], kh[3]);
                }
            }

            // mask (diag ktile only)
            const bool diag = ((kt >> 1) == qt);
            if (diag) {
                #pragma unroll
                for (int ni = 0; ni < 8; ni++) {
                    int gk = kt * 64 + ni * 8 + 2 * quad;
                    if (!(causal ? (gk     <= gq0) : (gk     >= gq0))) sc[ni][0] = -1e30f;
                    if (!(causal ? (gk + 1 <= gq0) : (gk + 1 >= gq0))) sc[ni][1] = -1e30f;
                    if (!(causal ? (gk     <= gq1) : (gk     >= gq1))) sc[ni][2] = -1e30f;
                    if (!(causal ? (gk + 1 <= gq1) : (gk + 1 >= gq1))) sc[ni][3] = -1e30f;
                }
            }

            // online softmax (log2 domain)
            float mt0 = -1e30f, mt1 = -1e30f;
            #pragma unroll
            for (int ni = 0; ni < 8; ni++) {
                mt0 = fmaxf(mt0, fmaxf(sc[ni][0], sc[ni][1]));
                mt1 = fmaxf(mt1, fmaxf(sc[ni][2], sc[ni][3]));
            }
            mt0 = fmaxf(mt0, __shfl_xor_sync(0xffffffffu, mt0, 1));
            mt0 = fmaxf(mt0, __shfl_xor_sync(0xffffffffu, mt0, 2));
            mt1 = fmaxf(mt1, __shfl_xor_sync(0xffffffffu, mt1, 1));
            mt1 = fmaxf(mt1, __shfl_xor_sync(0xffffffffu, mt1, 2));

            float mn0 = fmaxf(m0, mt0), mn1 = fmaxf(m1, mt1);
            float cr0 = ex2(m0 - mn0), cr1 = ex2(m1 - mn1);
            m0 = mn0; m1 = mn1;

            float ls0 = 0.f, ls1 = 0.f;
            #pragma unroll
            for (int ni = 0; ni < 8; ni++) {
                sc[ni][0] = ex2(sc[ni][0] - mn0);
                sc[ni][1] = ex2(sc[ni][1] - mn0);
                sc[ni][2] = ex2(sc[ni][2] - mn1);
                sc[ni][3] = ex2(sc[ni][3] - mn1);
                ls0 += sc[ni][0] + sc[ni][1];
                ls1 += sc[ni][2] + sc[ni][3];
            }
            ls0 += __shfl_xor_sync(0xffffffffu, ls0, 1);
            ls0 += __shfl_xor_sync(0xffffffffu, ls0, 2);
            ls1 += __shfl_xor_sync(0xffffffffu, ls1, 1);
            ls1 += __shfl_xor_sync(0xffffffffu, ls1, 2);
            l0 = l0 * cr0 + ls0;
            l1 = l1 * cr1 + ls1;

            #pragma unroll
            for (int ni = 0; ni < 8; ni++) {
                o[ni][0] *= cr0; o[ni][1] *= cr0;
                o[ni][2] *= cr1; o[ni][3] *= cr1;
            }

            // PV: O += P_hi * V_hi
            #pragma unroll
            for (int ks = 0; ks < 4; ks++) {
                unsigned ph2[4];
                {
                    __half2 hh;
                    hh = __floats2half2_rn(sc[2*ks][0],   sc[2*ks][1]);
                    ph2[0] = *reinterpret_cast<unsigned*>(&hh);
                    hh = __floats2half2_rn(sc[2*ks][2],   sc[2*ks][3]);
                    ph2[1] = *reinterpret_cast<unsigned*>(&hh);
                    hh = __floats2half2_rn(sc[2*ks+1][0], sc[2*ks+1][1]);
                    ph2[2] = *reinterpret_cast<unsigned*>(&hh);
                    hh = __floats2half2_rn(sc[2*ks+1][2], sc[2*ks+1][3]);
                    ph2[3] = *reinterpret_cast<unsigned*>(&hh);
                }
                #pragma unroll
                for (int np = 0; np < 4; np++) {
                    unsigned vh[4];
                    unsigned voff = ((ks * 16 + (lane & 15)) * KSTR
                                     + np * 16 + (lane >> 4) * 8) * 2;
                    ldsm4t(vh, kvb + AVH + voff);
                    mma16(o[2 * np],     ph2, vh[0], vh[1]);
                    mma16(o[2 * np + 1], ph2, vh[2], vh[3]);
                }
            }
        }

        // write O as fp16 hi (flat (B,H,N,E))
        float inv0 = 1.f / l0, inv1 = 1.f / l1;
        const size_t ob = ((size_t)b * 16 + h) * NTOK * HDIM;
        #pragma unroll
        for (int ni = 0; ni < 8; ni++) {
            int c = ni * 8 + 2 * quad;
            __half2 h0 = __floats2half2_rn(o[ni][0] * inv0, o[ni][1] * inv0);
            __half2 h1 = __floats2half2_rn(o[ni][2] * inv1, o[ni][3] * inv1);
            size_t i0 = ob + (size_t)gq0 * HDIM + c;
            size_t i1 = ob + (size_t)gq1 * HDIM + c;
            *reinterpret_cast<__half2*>(&Oh[i0]) = h0;
            *reinterpret_cast<__half2*>(&Oh[i1]) = h1;
        }
    }
}

// ---------------------------------------------------------------------------
extern "C" void kernel_launch(void* const* d_in, const int* in_sizes, int n_in,
                              void* d_out, int out_size) {
    const float* x     = (const float*)d_in[0];
    const float* Wq_lb = (const float*)d_in[1];
    const float* Wk_lb = (const float*)d_in[2];
    const float* Wv_lb = (const float*)d_in[3];
    const float* Wq_la = (const float*)d_in[4];
    const float* Wk_la = (const float*)d_in[5];
    const float* Wv_la = (const float*)d_in[6];
    const float* Wo    = (const float*)d_in[7];

    __half *xh, *xl, *wh, *qkvh, *oh;
    cudaGetSymbolAddress((void**)&xh, g_xh);
    cudaGetSymbolAddress((void**)&xl, g_xl);
    cudaGetSymbolAddress((void**)&wh, g_wh);
    cudaGetSymbolAddress((void**)&qkvh, g_qkvh);
    cudaGetSymbolAddress((void**)&oh, g_oh);

    presplit<<<8192, 256>>>(x, Wq_lb, Wq_la, Wk_lb, Wk_la, Wv_lb, Wv_la, Wo,
                            xh, xl, wh);

    cudaFuncSetAttribute(gemm_hl<0>,
                         cudaFuncAttributeMaxDynamicSharedMemorySize, GEMM_SMEM);
    cudaFuncSetAttribute(gemm_hl<1>,
                         cudaFuncAttributeMaxDynamicSharedMemorySize, GEMM_SMEM);
    cudaFuncSetAttribute(attn_hl,
                         cudaFuncAttributeMaxDynamicSharedMemorySize, ATTN_SMEM);

    gemm_hl<0><<<dim3(24, 32), 128, GEMM_SMEM>>>(xh, xl, wh, qkvh, nullptr);
    attn_hl<<<dim3(NTOK / 128, NHEAD / 2, BSZ), 256, ATTN_SMEM>>>(qkvh, oh);
    gemm_hl<1><<<dim3(8, 32), 128, GEMM_SMEM>>>(oh, nullptr, wh, nullptr,
                                                (float*)d_out);
}

// round 16
// speedup vs baseline: 1.0441x; 1.0441x over previous
#include <cuda_runtime.h>
#include <cuda_fp16.h>

#define BSZ   2
#define NTOK  2048
#define DIM   1024
#define NHEAD 16
#define HDIM  64

// fp16 scratch. Everything stored hi-only downstream of the projections;
// x keeps hi+lo (the lo pass protects Q_hi accuracy inside gemm0).
__device__ __half g_xh[4096 * 1024],  g_xl[4096 * 1024];
__device__ __half g_wh[4096 * 1024];
__device__ __half g_qkvh[3 * 4096 * 1024];
__device__ __half g_oh[4096 * 1024];

// Q pre-scale: 1/sqrt(64) * log2(e)  (softmax runs in log2 domain)
#define QSCALE 0.18033688011112042f

// ---------------- primitives ----------------------------------------------
__device__ __forceinline__ void split2v(float x, float y, __half2& h, __half2& l) {
    h = __floats2half2_rn(x, y);
    float2 f = __half22float2(h);
    l = __floats2half2_rn(x - f.x, y - f.y);
}
__device__ __forceinline__ float ex2(float x) {
    float r;
    asm("ex2.approx.f32 %0, %1;" : "=f"(r) : "f"(x));
    return r;
}
__device__ __forceinline__ void mma16(float* c, const unsigned* a,
                                      unsigned b0, unsigned b1) {
    asm volatile(
        "mma.sync.aligned.m16n8k16.row.col.f32.f16.f16.f32 "
        "{%0,%1,%2,%3}, {%4,%5,%6,%7}, {%8,%9}, {%0,%1,%2,%3};"
        : "+f"(c[0]), "+f"(c[1]), "+f"(c[2]), "+f"(c[3])
        : "r"(a[0]), "r"(a[1]), "r"(a[2]), "r"(a[3]), "r"(b0), "r"(b1));
}
__device__ __forceinline__ void ldsm4(unsigned* r, unsigned addr) {
    asm volatile("ldmatrix.sync.aligned.m8n8.x4.shared.b16 {%0,%1,%2,%3}, [%4];"
        : "=r"(r[0]), "=r"(r[1]), "=r"(r[2]), "=r"(r[3]) : "r"(addr));
}
__device__ __forceinline__ void ldsm4t(unsigned* r, unsigned addr) {
    asm volatile("ldmatrix.sync.aligned.m8n8.x4.trans.shared.b16 {%0,%1,%2,%3}, [%4];"
        : "=r"(r[0]), "=r"(r[1]), "=r"(r[2]), "=r"(r[3]) : "r"(addr));
}
__device__ __forceinline__ void cpa(unsigned dst, const void* src) {
    asm volatile("cp.async.cg.shared.global [%0], [%1], 16;" :: "r"(dst), "l"(src));
}
__device__ __forceinline__ void cpcommit() { asm volatile("cp.async.commit_group;"); }
template <int N> __device__ __forceinline__ void cpwait() {
    asm volatile("cp.async.wait_group %0;" :: "n"(N));
}

// ---------------- pre-split pass (x and W fused) -----------------------------
__global__ void presplit(const float* __restrict__ x,
                         const float* __restrict__ W0, const float* __restrict__ W1,
                         const float* __restrict__ W2, const float* __restrict__ W3,
                         const float* __restrict__ W4, const float* __restrict__ W5,
                         const float* __restrict__ W6,
                         __half* __restrict__ xh, __half* __restrict__ xl,
                         __half* __restrict__ wh) {
    if (blockIdx.x < 4096) {
        int id = blockIdx.x * 256 + threadIdx.x;
        float4 v = reinterpret_cast<const float4*>(x)[id];
        __half2 h0, l0, h1, l1;
        split2v(v.x, v.y, h0, l0);
        split2v(v.z, v.w, h1, l1);
        reinterpret_cast<__half2*>(xh)[id * 2]     = h0;
        reinterpret_cast<__half2*>(xh)[id * 2 + 1] = h1;
        reinterpret_cast<__half2*>(xl)[id * 2]     = l0;
        reinterpret_cast<__half2*>(xl)[id * 2 + 1] = l1;
    } else {
        int id  = (blockIdx.x - 4096) * 256 + threadIdx.x;
        int row = id >> 8;
        int q   = id & 255;
        const float* src;
        int rr;
        if (row < 3072) {
            int t = row >> 9;
            src = (t == 0) ? W0 : (t == 1) ? W1 : (t == 2) ? W2
                : (t == 3) ? W3 : (t == 4) ? W4 : W5;
            rr = row & 511;
        } else {
            src = W6; rr = row - 3072;
        }
        float4 v = reinterpret_cast<const float4*>(src + (size_t)rr * DIM)[q];
        __half2 h0 = __floats2half2_rn(v.x, v.y);
        __half2 h1 = __floats2half2_rn(v.z, v.w);
        reinterpret_cast<__half2*>(wh)[id * 2]     = h0;
        reinterpret_cast<__half2*>(wh)[id * 2 + 1] = h1;
    }
}

// ---------------------------------------------------------------------------
// fp16x2 GEMM: C = (A_hi [+ A_lo]) * W_hi^T.  8 warps, 64x32 warp tiles
// (R14 config — best measured). cp.async multistage pipeline, one
// __syncthreads per k-stage.
//   MODE 0 (QKV): stage = A_hi|A_lo|B_hi (30720B), 3 stages; A_lo pass only
//                 for Q column tiles (blockIdx.x < 8).
//   MODE 1 (out-proj, hi-only): stage = A_hi|B_hi (20480B), 5 stages —
//                 deeper lookahead for the latency-exposed single-wave GEMM.
// ---------------------------------------------------------------------------
#define GSTR 40
#define GEMM0_SMEM (3 * 30720)
#define GEMM1_SMEM (5 * 20480)

template <int MODE>
__global__ void __launch_bounds__(256, 2)
gemm_hl(const __half* __restrict__ Ah, const __half* __restrict__ Al,
        const __half* __restrict__ Wh,
        __half* __restrict__ Ch,
        float* __restrict__ Cf) {
    extern __shared__ __half smx[];
    const unsigned sbase = (unsigned)__cvta_generic_to_shared(smx);

    constexpr int      NSTAGE = (MODE == 0) ? 3 : 5;
    constexpr unsigned STAGEB = (MODE == 0) ? 30720u : 20480u;
    constexpr unsigned BOFF   = (MODE == 0) ? 20480u : 10240u;

    const int tid  = threadIdx.x;
    const int lane = tid & 31;
    const int wid  = tid >> 5;
    const int wm   = (wid >> 2) * 64;
    const int wn   = (wid & 3) * 32;
    const int row0 = blockIdx.y * 128;
    const int col0 = blockIdx.x * 128;
    const int wrow0 = (MODE == 0) ? col0 : (col0 + 3072);
    const bool doLo = (MODE == 0) && (blockIdx.x < 8);   // Q tiles only

    const int crow = tid >> 2;
    const int ckc  = tid & 3;

    auto issue = [&](int s) {
        const unsigned stb = sbase + (unsigned)((s % NSTAGE) * STAGEB);
        const int k0 = s * 32;
        #pragma unroll
        for (int i = 0; i < 2; i++) {
            int row = crow + i * 64;
            unsigned doff = row * 80 + ckc * 16;
            size_t soffA = (size_t)(row0 + row) * DIM + k0 + ckc * 8;
            size_t soffB = (size_t)(wrow0 + row) * DIM + k0 + ckc * 8;
            cpa(stb + doff,        Ah + soffA);
            if (doLo) cpa(stb + 10240 + doff, Al + soffA);
            cpa(stb + BOFF + doff, Wh + soffB);
        }
        cpcommit();
    };

    float acc[4][4][4] = {};

    #pragma unroll
    for (int i = 0; i < NSTAGE - 1; i++) issue(i);

    #pragma unroll 1
    for (int s = 0; s < 32; s++) {
        if (s < 32 - (NSTAGE - 1)) cpwait<NSTAGE - 2>(); else cpwait<0>();
        __syncthreads();
        if (s + NSTAGE - 1 < 32) issue(s + NSTAGE - 1);

        const unsigned stb = sbase + (unsigned)((s % NSTAGE) * STAGEB);
        #pragma unroll
        for (int ks = 0; ks < 2; ks++) {
            unsigned bh[2][4];
            #pragma unroll
            for (int np = 0; np < 2; np++) {
                unsigned off = stb + BOFF +
                    ((wn + np * 16 + (lane >> 4) * 8 + (lane & 7)) * GSTR
                     + ks * 16 + ((lane >> 3) & 1) * 8) * 2;
                ldsm4(bh[np], off);
            }
            #pragma unroll
            for (int mi = 0; mi < 4; mi++) {
                unsigned ah[4], al[4];
                unsigned off = stb + ((wm + mi * 16 + (lane & 15)) * GSTR
                                      + ks * 16 + (lane >> 4) * 8) * 2;
                ldsm4(ah, off);
                if (doLo) ldsm4(al, off + 10240);
                #pragma unroll
                for (int ni = 0; ni < 4; ni++) {
                    unsigned b0 = bh[ni >> 1][(ni & 1) * 2];
                    unsigned b1 = bh[ni >> 1][(ni & 1) * 2 + 1];
                    mma16(acc[mi][ni], ah, b0, b1);
                    if (doLo) mma16(acc[mi][ni], al, b0, b1);
                }
            }
        }
    }

    // epilogue
    #pragma unroll
    for (int mi = 0; mi < 4; mi++) {
        int r = row0 + wm + mi * 16 + (lane >> 2);
        #pragma unroll
        for (int ni = 0; ni < 4; ni++) {
            int c = col0 + wn + ni * 8 + 2 * (lane & 3);
            if (MODE == 0) {
                int m = c >> 10, j = c & 1023;
                float qs = (m == 0) ? QSCALE : 1.0f;   // Q pre-scale
                __half2 h0 = __floats2half2_rn(acc[mi][ni][0] * qs,
                                               acc[mi][ni][1] * qs);
                __half2 h1 = __floats2half2_rn(acc[mi][ni][2] * qs,
                                               acc[mi][ni][3] * qs);
                int hh = j >> 6, e = j & 63;
                int b = r >> 11, n = r & 2047;
                size_t idx = ((((size_t)(m * 2 + b) * 16 + hh) * NTOK) + n) * HDIM + e;
                *reinterpret_cast<__half2*>(&Ch[idx])            = h0;
                *reinterpret_cast<__half2*>(&Ch[idx + 8 * HDIM]) = h1;
            } else {
                float2 v0 = make_float2(acc[mi][ni][0], acc[mi][ni][1]);
                float2 v1 = make_float2(acc[mi][ni][2], acc[mi][ni][3]);
                *reinterpret_cast<float2*>(&Cf[(size_t)r * DIM + c])       = v0;
                *reinterpret_cast<float2*>(&Cf[(size_t)(r + 8) * DIM + c]) = v1;
            }
        }
    }
}

// ---------------------------------------------------------------------------
// fp16 flash attention (hi-only operands), 2-phase load-balanced, 3-buffer
// single-barrier pipeline. Fully-masked diag ktiles skipped per-warp.
// smem: Q_hi (18432) | 3 x KV buffer (K 9216 + V 9216)
// ---------------------------------------------------------------------------
#define AQH   0u
#define ABUF  18432u
#define ABUFSZ 18432u
#define AKH   0u
#define AVH   9216u
#define ATTN_SMEM 73728
#define KSTR  72

__global__ void __launch_bounds__(256, 2)
attn_hl(const __half* __restrict__ QKVh, __half* __restrict__ Oh) {
    extern __shared__ __half sma[];
    const unsigned sbase = (unsigned)__cvta_generic_to_shared(sma);

    const int qt  = blockIdx.x;     // 0..15 (128-row q tiles)
    const int b   = blockIdx.z;
    const int tid  = threadIdx.x;
    const int lane = tid & 31;
    const int w    = tid >> 5;
    const int quad = lane & 3;
    const int gpr  = lane >> 2;

    const int gq0 = qt * 128 + w * 16 + gpr;
    const int gq1 = gq0 + 8;

    #pragma unroll 1
    for (int ph = 0; ph < 2; ph++) {
        const int h = blockIdx.y + ph * 8;
        const bool causal = (ph == 0);

        const size_t hb = ((size_t)b * 16 + h) * NTOK * HDIM;
        const __half* Qgh = QKVh + hb;
        const __half* Kgh = QKVh + 2 * 2048 * 1024 + hb;
        const __half* Vgh = QKVh + 4 * 2048 * 1024 + hb;

        const int kt0 = causal ? 0 : (2 * qt);
        const int kt1 = causal ? (2 * qt + 1) : (NTOK / 64 - 1);

        auto issue_kv = [&](int kt, int buf) {
            #pragma unroll
            for (int i = 0; i < 2; i++) {
                int c = tid + i * 256;
                int key = c >> 3, ec = c & 7;
                size_t soff = (size_t)(kt * 64 + key) * HDIM + ec * 8;
                unsigned doff = sbase + ABUF + buf * ABUFSZ + key * 144 + ec * 16;
                cpa(doff + AKH, Kgh + soff);
                cpa(doff + AVH, Vgh + soff);
            }
            cpcommit();
        };

        // barrier: previous phase (or nothing) fully done with smem
        __syncthreads();

        // prologue: Q tile (128 rows x 8 chunks = 1024 chunks) + KV tile kt0
        // in group 0; KV kt0+1 in group 1
        {
            #pragma unroll
            for (int i = 0; i < 4; i++) {
                int c = tid + i * 256;                // 0..1023
                int row = c >> 3, ec = c & 7;
                size_t soff = (size_t)(qt * 128 + row) * HDIM + ec * 8;
                cpa(sbase + AQH + row * 144 + ec * 16, Qgh + soff);
            }
            #pragma unroll
            for (int i = 0; i < 2; i++) {
                int c = tid + i * 256;
                int key = c >> 3, ec = c & 7;
                size_t soff = (size_t)(kt0 * 64 + key) * HDIM + ec * 8;
                unsigned doff = sbase + ABUF + 0 * ABUFSZ + key * 144 + ec * 16;
                cpa(doff + AKH, Kgh + soff);
                cpa(doff + AVH, Vgh + soff);
            }
            cpcommit();
        }
        if (kt0 + 1 <= kt1) issue_kv(kt0 + 1, 1);

        float o[8][4] = {};
        float m0 = -1e30f, m1 = -1e30f, l0 = 0.f, l1 = 0.f;

        #pragma unroll 1
        for (int kt = kt0; kt <= kt1; kt++) {
            const int i3 = (kt - kt0) % 3;
            if (kt < kt1) cpwait<1>(); else cpwait<0>();
            __syncthreads();
            if (kt + 2 <= kt1) issue_kv(kt + 2, (i3 + 2) % 3);

            // warp-granular skip of fully-masked diag ktile (exact no-op)
            const bool skipw = causal ? (kt == 2 * qt + 1 && w < 4)
                                      : (kt == 2 * qt && w >= 4);
            if (skipw) continue;

            const unsigned kvb = sbase + ABUF + i3 * ABUFSZ;

            // S = Q_hi K_hi^T (log2 domain)
            float sc[8][4] = {};
            #pragma unroll
            for (int ks = 0; ks < 4; ks++) {
                unsigned qh[4];
                unsigned qoff = ((w * 16 + (lane & 15)) * KSTR
                                 + ks * 16 + (lane >> 4) * 8) * 2;
                ldsm4(qh, sbase + AQH + qoff);
                #pragma unroll
                for (int np = 0; np < 4; np++) {
                    unsigned kh[4];
                    unsigned koff = ((np * 16 + (lane >> 4) * 8 + (lane & 7)) * KSTR
                                     + ks * 16 + ((lane >> 3) & 1) * 8) * 2;
                    ldsm4(kh, kvb + AKH + koff);
                    mma16(sc[2 * np],     qh, kh[0], kh[1]);
                    mma16(sc[2 * np + 1], qh, kh[2], kh[3]);
                }
            }

            // mask (diag ktile only)
            const bool diag = ((kt >> 1) == qt);
            if (diag) {
                #pragma unroll
                for (int ni = 0; ni < 8; ni++) {
                    int gk = kt * 64 + ni * 8 + 2 * quad;
                    if (!(causal ? (gk     <= gq0) : (gk     >= gq0))) sc[ni][0] = -1e30f;
                    if (!(causal ? (gk + 1 <= gq0) : (gk + 1 >= gq0))) sc[ni][1] = -1e30f;
                    if (!(causal ? (gk     <= gq1) : (gk     >= gq1))) sc[ni][2] = -1e30f;
                    if (!(causal ? (gk + 1 <= gq1) : (gk + 1 >= gq1))) sc[ni][3] = -1e30f;
                }
            }

            // online softmax (log2 domain)
            float mt0 = -1e30f, mt1 = -1e30f;
            #pragma unroll
            for (int ni = 0; ni < 8; ni++) {
                mt0 = fmaxf(mt0, fmaxf(sc[ni][0], sc[ni][1]));
                mt1 = fmaxf(mt1, fmaxf(sc[ni][2], sc[ni][3]));
            }
            mt0 = fmaxf(mt0, __shfl_xor_sync(0xffffffffu, mt0, 1));
            mt0 = fmaxf(mt0, __shfl_xor_sync(0xffffffffu, mt0, 2));
            mt1 = fmaxf(mt1, __shfl_xor_sync(0xffffffffu, mt1, 1));
            mt1 = fmaxf(mt1, __shfl_xor_sync(0xffffffffu, mt1, 2));

            float mn0 = fmaxf(m0, mt0), mn1 = fmaxf(m1, mt1);
            float cr0 = ex2(m0 - mn0), cr1 = ex2(m1 - mn1);
            m0 = mn0; m1 = mn1;

            float ls0 = 0.f, ls1 = 0.f;
            #pragma unroll
            for (int ni = 0; ni < 8; ni++) {
                sc[ni][0] = ex2(sc[ni][0] - mn0);
                sc[ni][1] = ex2(sc[ni][1] - mn0);
                sc[ni][2] = ex2(sc[ni][2] - mn1);
                sc[ni][3] = ex2(sc[ni][3] - mn1);
                ls0 += sc[ni][0] + sc[ni][1];
                ls1 += sc[ni][2] + sc[ni][3];
            }
            ls0 += __shfl_xor_sync(0xffffffffu, ls0, 1);
            ls0 += __shfl_xor_sync(0xffffffffu, ls0, 2);
            ls1 += __shfl_xor_sync(0xffffffffu, ls1, 1);
            ls1 += __shfl_xor_sync(0xffffffffu, ls1, 2);
            l0 = l0 * cr0 + ls0;
            l1 = l1 * cr1 + ls1;

            #pragma unroll
            for (int ni = 0; ni < 8; ni++) {
                o[ni][0] *= cr0; o[ni][1] *= cr0;
                o[ni][2] *= cr1; o[ni][3] *= cr1;
            }

            // PV: O += P_hi * V_hi
            #pragma unroll
            for (int ks = 0; ks < 4; ks++) {
                unsigned ph2[4];
                {
                    __half2 hh;
                    hh = __floats2half2_rn(sc[2*ks][0],   sc[2*ks][1]);
                    ph2[0] = *reinterpret_cast<unsigned*>(&hh);
                    hh = __floats2half2_rn(sc[2*ks][2],   sc[2*ks][3]);
                    ph2[1] = *reinterpret_cast<unsigned*>(&hh);
                    hh = __floats2half2_rn(sc[2*ks+1][0], sc[2*ks+1][1]);
                    ph2[2] = *reinterpret_cast<unsigned*>(&hh);
                    hh = __floats2half2_rn(sc[2*ks+1][2], sc[2*ks+1][3]);
                    ph2[3] = *reinterpret_cast<unsigned*>(&hh);
                }
                #pragma unroll
                for (int np = 0; np < 4; np++) {
                    unsigned vh[4];
                    unsigned voff = ((ks * 16 + (lane & 15)) * KSTR
                                     + np * 16 + (lane >> 4) * 8) * 2;
                    ldsm4t(vh, kvb + AVH + voff);
                    mma16(o[2 * np],     ph2, vh[0], vh[1]);
                    mma16(o[2 * np + 1], ph2, vh[2], vh[3]);
                }
            }
        }

        // write O as fp16 hi (flat (B,H,N,E))
        float inv0 = 1.f / l0, inv1 = 1.f / l1;
        const size_t ob = ((size_t)b * 16 + h) * NTOK * HDIM;
        #pragma unroll
        for (int ni = 0; ni < 8; ni++) {
            int c = ni * 8 + 2 * quad;
            __half2 h0 = __floats2half2_rn(o[ni][0] * inv0, o[ni][1] * inv0);
            __half2 h1 = __floats2half2_rn(o[ni][2] * inv1, o[ni][3] * inv1);
            size_t i0 = ob + (size_t)gq0 * HDIM + c;
            size_t i1 = ob + (size_t)gq1 * HDIM + c;
            *reinterpret_cast<__half2*>(&Oh[i0]) = h0;
            *reinterpret_cast<__half2*>(&Oh[i1]) = h1;
        }
    }
}

// ---------------------------------------------------------------------------
extern "C" void kernel_launch(void* const* d_in, const int* in_sizes, int n_in,
                              void* d_out, int out_size) {
    const float* x     = (const float*)d_in[0];
    const float* Wq_lb = (const float*)d_in[1];
    const float* Wk_lb = (const float*)d_in[2];
    const float* Wv_lb = (const float*)d_in[3];
    const float* Wq_la = (const float*)d_in[4];
    const float* Wk_la = (const float*)d_in[5];
    const float* Wv_la = (const float*)d_in[6];
    const float* Wo    = (const float*)d_in[7];

    __half *xh, *xl, *wh, *qkvh, *oh;
    cudaGetSymbolAddress((void**)&xh, g_xh);
    cudaGetSymbolAddress((void**)&xl, g_xl);
    cudaGetSymbolAddress((void**)&wh, g_wh);
    cudaGetSymbolAddress((void**)&qkvh, g_qkvh);
    cudaGetSymbolAddress((void**)&oh, g_oh);

    presplit<<<8192, 256>>>(x, Wq_lb, Wq_la, Wk_lb, Wk_la, Wv_lb, Wv_la, Wo,
                            xh, xl, wh);

    cudaFuncSetAttribute(gemm_hl<0>,
                         cudaFuncAttributeMaxDynamicSharedMemorySize, GEMM0_SMEM);
    cudaFuncSetAttribute(gemm_hl<1>,
                         cudaFuncAttributeMaxDynamicSharedMemorySize, GEMM1_SMEM);
    cudaFuncSetAttribute(attn_hl,
                         cudaFuncAttributeMaxDynamicSharedMemorySize, ATTN_SMEM);

    gemm_hl<0><<<dim3(24, 32), 256, GEMM0_SMEM>>>(xh, xl, wh, qkvh, nullptr);
    attn_hl<<<dim3(NTOK / 128, NHEAD / 2, BSZ), 256, ATTN_SMEM>>>(qkvh, oh);
    gemm_hl<1><<<dim3(8, 32), 256, GEMM1_SMEM>>>(oh, nullptr, wh, nullptr,
                                                 (float*)d_out);
}

// round 17
// speedup vs baseline: 1.1967x; 1.1461x over previous
#include <cuda_runtime.h>
#include <cuda_fp16.h>

#define BSZ   2
#define NTOK  2048
#define DIM   1024
#define NHEAD 16
#define HDIM  64

// fp16 scratch. Everything stored hi-only downstream of the projections;
// x keeps hi+lo (the lo pass protects Q_hi accuracy inside the Q proj).
__device__ __half g_xh[4096 * 1024],  g_xl[4096 * 1024];
__device__ __half g_wh[4096 * 1024];
__device__ __half g_qkvh[3 * 4096 * 1024];
__device__ __half g_oh[4096 * 1024];

// Q pre-scale: 1/sqrt(64) * log2(e)  (softmax runs in log2 domain)
#define QSCALE 0.18033688011112042f

// ---------------- primitives ----------------------------------------------
__device__ __forceinline__ void split2v(float x, float y, __half2& h, __half2& l) {
    h = __floats2half2_rn(x, y);
    float2 f = __half22float2(h);
    l = __floats2half2_rn(x - f.x, y - f.y);
}
__device__ __forceinline__ float ex2(float x) {
    float r;
    asm("ex2.approx.f32 %0, %1;" : "=f"(r) : "f"(x));
    return r;
}
__device__ __forceinline__ void mma16(float* c, const unsigned* a,
                                      unsigned b0, unsigned b1) {
    asm volatile(
        "mma.sync.aligned.m16n8k16.row.col.f32.f16.f16.f32 "
        "{%0,%1,%2,%3}, {%4,%5,%6,%7}, {%8,%9}, {%0,%1,%2,%3};"
        : "+f"(c[0]), "+f"(c[1]), "+f"(c[2]), "+f"(c[3])
        : "r"(a[0]), "r"(a[1]), "r"(a[2]), "r"(a[3]), "r"(b0), "r"(b1));
}
__device__ __forceinline__ void ldsm4(unsigned* r, unsigned addr) {
    asm volatile("ldmatrix.sync.aligned.m8n8.x4.shared.b16 {%0,%1,%2,%3}, [%4];"
        : "=r"(r[0]), "=r"(r[1]), "=r"(r[2]), "=r"(r[3]) : "r"(addr));
}
__device__ __forceinline__ void ldsm4t(unsigned* r, unsigned addr) {
    asm volatile("ldmatrix.sync.aligned.m8n8.x4.trans.shared.b16 {%0,%1,%2,%3}, [%4];"
        : "=r"(r[0]), "=r"(r[1]), "=r"(r[2]), "=r"(r[3]) : "r"(addr));
}
__device__ __forceinline__ void cpa(unsigned dst, const void* src) {
    asm volatile("cp.async.cg.shared.global [%0], [%1], 16;" :: "r"(dst), "l"(src));
}
__device__ __forceinline__ void cpcommit() { asm volatile("cp.async.commit_group;"); }
template <int N> __device__ __forceinline__ void cpwait() {
    asm volatile("cp.async.wait_group %0;" :: "n"(N));
}

// ---------------- pre-split pass (x and W fused) -----------------------------
__global__ void presplit(const float* __restrict__ x,
                         const float* __restrict__ W0, const float* __restrict__ W1,
                         const float* __restrict__ W2, const float* __restrict__ W3,
                         const float* __restrict__ W4, const float* __restrict__ W5,
                         const float* __restrict__ W6,
                         __half* __restrict__ xh, __half* __restrict__ xl,
                         __half* __restrict__ wh) {
    if (blockIdx.x < 4096) {
        int id = blockIdx.x * 256 + threadIdx.x;
        float4 v = reinterpret_cast<const float4*>(x)[id];
        __half2 h0, l0, h1, l1;
        split2v(v.x, v.y, h0, l0);
        split2v(v.z, v.w, h1, l1);
        reinterpret_cast<__half2*>(xh)[id * 2]     = h0;
        reinterpret_cast<__half2*>(xh)[id * 2 + 1] = h1;
        reinterpret_cast<__half2*>(xl)[id * 2]     = l0;
        reinterpret_cast<__half2*>(xl)[id * 2 + 1] = l1;
    } else {
        int id  = (blockIdx.x - 4096) * 256 + threadIdx.x;
        int row = id >> 8;
        int q   = id & 255;
        const float* src;
        int rr;
        if (row < 3072) {
            int t = row >> 9;
            src = (t == 0) ? W0 : (t == 1) ? W1 : (t == 2) ? W2
                : (t == 3) ? W3 : (t == 4) ? W4 : W5;
            rr = row & 511;
        } else {
            src = W6; rr = row - 3072;
        }
        float4 v = reinterpret_cast<const float4*>(src + (size_t)rr * DIM)[q];
        __half2 h0 = __floats2half2_rn(v.x, v.y);
        __half2 h1 = __floats2half2_rn(v.z, v.w);
        reinterpret_cast<__half2*>(wh)[id * 2]     = h0;
        reinterpret_cast<__half2*>(wh)[id * 2 + 1] = h1;
    }
}

// ---------------------------------------------------------------------------
// fp16x2 GEMM family. 8 warps, 64x32 warp tiles, 3-stage cp.async pipeline,
// one __syncthreads per k-stage.
//   MODE 0 (Q proj, hi+lo):  BK=32 stages (proven config), scatter + QSCALE.
//   MODE 1 (KV proj, hi):    BK=64 stages (128 MMAs/warp/barrier), scatter.
//   MODE 2 (out proj, hi):   BK=64 stages, fp32 row-major epilogue.
// BK=64 smem rows use the attention-proven 144B stride (conflict-free LDSM).
// ---------------------------------------------------------------------------
#define GEMMQ_SMEM  (3 * 30720)
#define GEMM64_SMEM (3 * 36864)

template <int MODE>
__global__ void __launch_bounds__(256, 2)
gemm_hl(const __half* __restrict__ Ah, const __half* __restrict__ Al,
        const __half* __restrict__ Wh,
        __half* __restrict__ Ch,
        float* __restrict__ Cf) {
    extern __shared__ __half smx[];
    const unsigned sbase = (unsigned)__cvta_generic_to_shared(smx);

    constexpr int      KST    = (MODE == 0) ? 32 : 16;       // k-stages
    constexpr int      NKS    = (MODE == 0) ? 2 : 4;         // 16-k slices/stage
    constexpr unsigned STAGEB = (MODE == 0) ? 30720u : 36864u;
    constexpr unsigned BOFF   = (MODE == 0) ? 20480u : 18432u;
    constexpr int      STRH   = (MODE == 0) ? 40 : 72;       // halfs per row

    const int tid  = threadIdx.x;
    const int lane = tid & 31;
    const int wid  = tid >> 5;
    const int wm   = (wid >> 2) * 64;
    const int wn   = (wid & 3) * 32;
    const int row0 = blockIdx.y * 128;
    const int col0 = blockIdx.x * 128;
    const int wrow0 = (MODE == 0) ? col0 : (MODE == 1) ? (col0 + 1024)
                                         : (col0 + 3072);

    auto issue = [&](int s) {
        const unsigned stb = sbase + (unsigned)((s % 3) * STAGEB);
        if (MODE == 0) {
            const int k0 = s * 32;
            const int crow = tid >> 2;
            const int ckc  = tid & 3;
            #pragma unroll
            for (int i = 0; i < 2; i++) {
                int row = crow + i * 64;
                unsigned doff = row * 80 + ckc * 16;
                size_t soffA = (size_t)(row0 + row) * DIM + k0 + ckc * 8;
                size_t soffB = (size_t)(wrow0 + row) * DIM + k0 + ckc * 8;
                cpa(stb + doff,         Ah + soffA);
                cpa(stb + 10240 + doff, Al + soffA);
                cpa(stb + 20480 + doff, Wh + soffB);
            }
        } else {
            const int k0 = s * 64;
            #pragma unroll
            for (int i = 0; i < 4; i++) {
                int id = tid + i * 256;            // 0..1023
                int row = id >> 3, c8 = id & 7;
                unsigned doff = row * 144 + c8 * 16;
                size_t soffA = (size_t)(row0 + row) * DIM + k0 + c8 * 8;
                size_t soffB = (size_t)(wrow0 + row) * DIM + k0 + c8 * 8;
                cpa(stb + doff,        Ah + soffA);
                cpa(stb + BOFF + doff, Wh + soffB);
            }
        }
        cpcommit();
    };

    float acc[4][4][4] = {};

    issue(0);
    issue(1);

    #pragma unroll 1
    for (int s = 0; s < KST; s++) {
        if (s < KST - 2) cpwait<1>(); else cpwait<0>();
        __syncthreads();
        if (s + 2 < KST) issue(s + 2);

        const unsigned stb = sbase + (unsigned)((s % 3) * STAGEB);
        #pragma unroll
        for (int ks = 0; ks < NKS; ks++) {
            unsigned bh[2][4];
            #pragma unroll
            for (int np = 0; np < 2; np++) {
                unsigned off = stb + BOFF +
                    ((wn + np * 16 + (lane >> 4) * 8 + (lane & 7)) * STRH
                     + ks * 16 + ((lane >> 3) & 1) * 8) * 2;
                ldsm4(bh[np], off);
            }
            #pragma unroll
            for (int mi = 0; mi < 4; mi++) {
                unsigned ah[4], al[4];
                unsigned off = stb + ((wm + mi * 16 + (lane & 15)) * STRH
                                      + ks * 16 + (lane >> 4) * 8) * 2;
                ldsm4(ah, off);
                if (MODE == 0) ldsm4(al, off + 10240);
                #pragma unroll
                for (int ni = 0; ni < 4; ni++) {
                    unsigned b0 = bh[ni >> 1][(ni & 1) * 2];
                    unsigned b1 = bh[ni >> 1][(ni & 1) * 2 + 1];
                    mma16(acc[mi][ni], ah, b0, b1);
                    if (MODE == 0) mma16(acc[mi][ni], al, b0, b1);
                }
            }
        }
    }

    // epilogue
    #pragma unroll
    for (int mi = 0; mi < 4; mi++) {
        int r = row0 + wm + mi * 16 + (lane >> 2);
        #pragma unroll
        for (int ni = 0; ni < 4; ni++) {
            int cl = col0 + wn + ni * 8 + 2 * (lane & 3);
            if (MODE == 2) {
                float2 v0 = make_float2(acc[mi][ni][0], acc[mi][ni][1]);
                float2 v1 = make_float2(acc[mi][ni][2], acc[mi][ni][3]);
                *reinterpret_cast<float2*>(&Cf[(size_t)r * DIM + cl])       = v0;
                *reinterpret_cast<float2*>(&Cf[(size_t)(r + 8) * DIM + cl]) = v1;
            } else {
                int c = (MODE == 0) ? cl : (cl + 1024);
                int m = c >> 10, j = c & 1023;
                float qs = (MODE == 0) ? QSCALE : 1.0f;
                __half2 h0 = __floats2half2_rn(acc[mi][ni][0] * qs,
                                               acc[mi][ni][1] * qs);
                __half2 h1 = __floats2half2_rn(acc[mi][ni][2] * qs,
                                               acc[mi][ni][3] * qs);
                int hh = j >> 6, e = j & 63;
                int b = r >> 11, n = r & 2047;
                size_t idx = ((((size_t)(m * 2 + b) * 16 + hh) * NTOK) + n) * HDIM + e;
                *reinterpret_cast<__half2*>(&Ch[idx])            = h0;
                *reinterpret_cast<__half2*>(&Ch[idx + 8 * HDIM]) = h1;
            }
        }
    }
}

// ---------------------------------------------------------------------------
// fp16 flash attention (hi-only operands), 2-phase load-balanced, 3-buffer
// single-barrier pipeline. Fully-masked diag ktiles skipped per-warp.
// smem: Q_hi (18432) | 3 x KV buffer (K 9216 + V 9216)
// ---------------------------------------------------------------------------
#define AQH   0u
#define ABUF  18432u
#define ABUFSZ 18432u
#define AKH   0u
#define AVH   9216u
#define ATTN_SMEM 73728
#define KSTR  72

__global__ void __launch_bounds__(256, 2)
attn_hl(const __half* __restrict__ QKVh, __half* __restrict__ Oh) {
    extern __shared__ __half sma[];
    const unsigned sbase = (unsigned)__cvta_generic_to_shared(sma);

    const int qt  = blockIdx.x;     // 0..15 (128-row q tiles)
    const int b   = blockIdx.z;
    const int tid  = threadIdx.x;
    const int lane = tid & 31;
    const int w    = tid >> 5;
    const int quad = lane & 3;
    const int gpr  = lane >> 2;

    const int gq0 = qt * 128 + w * 16 + gpr;
    const int gq1 = gq0 + 8;

    #pragma unroll 1
    for (int ph = 0; ph < 2; ph++) {
        const int h = blockIdx.y + ph * 8;
        const bool causal = (ph == 0);

        const size_t hb = ((size_t)b * 16 + h) * NTOK * HDIM;
        const __half* Qgh = QKVh + hb;
        const __half* Kgh = QKVh + 2 * 2048 * 1024 + hb;
        const __half* Vgh = QKVh + 4 * 2048 * 1024 + hb;

        const int kt0 = causal ? 0 : (2 * qt);
        const int kt1 = causal ? (2 * qt + 1) : (NTOK / 64 - 1);

        auto issue_kv = [&](int kt, int buf) {
            #pragma unroll
            for (int i = 0; i < 2; i++) {
                int c = tid + i * 256;
                int key = c >> 3, ec = c & 7;
                size_t soff = (size_t)(kt * 64 + key) * HDIM + ec * 8;
                unsigned doff = sbase + ABUF + buf * ABUFSZ + key * 144 + ec * 16;
                cpa(doff + AKH, Kgh + soff);
                cpa(doff + AVH, Vgh + soff);
            }
            cpcommit();
        };

        // barrier: previous phase (or nothing) fully done with smem
        __syncthreads();

        // prologue: Q tile (128 rows x 8 chunks = 1024 chunks) + KV tile kt0
        // in group 0; KV kt0+1 in group 1
        {
            #pragma unroll
            for (int i = 0; i < 4; i++) {
                int c = tid + i * 256;                // 0..1023
                int row = c >> 3, ec = c & 7;
                size_t soff = (size_t)(qt * 128 + row) * HDIM + ec * 8;
                cpa(sbase + AQH + row * 144 + ec * 16, Qgh + soff);
            }
            #pragma unroll
            for (int i = 0; i < 2; i++) {
                int c = tid + i * 256;
                int key = c >> 3, ec = c & 7;
                size_t soff = (size_t)(kt0 * 64 + key) * HDIM + ec * 8;
                unsigned doff = sbase + ABUF + 0 * ABUFSZ + key * 144 + ec * 16;
                cpa(doff + AKH, Kgh + soff);
                cpa(doff + AVH, Vgh + soff);
            }
            cpcommit();
        }
        if (kt0 + 1 <= kt1) issue_kv(kt0 + 1, 1);

        float o[8][4] = {};
        float m0 = -1e30f, m1 = -1e30f, l0 = 0.f, l1 = 0.f;

        #pragma unroll 1
        for (int kt = kt0; kt <= kt1; kt++) {
            const int i3 = (kt - kt0) % 3;
            if (kt < kt1) cpwait<1>(); else cpwait<0>();
            __syncthreads();
            if (kt + 2 <= kt1) issue_kv(kt + 2, (i3 + 2) % 3);

            // warp-granular skip of fully-masked diag ktile (exact no-op)
            const bool skipw = causal ? (kt == 2 * qt + 1 && w < 4)
                                      : (kt == 2 * qt && w >= 4);
            if (skipw) continue;

            const unsigned kvb = sbase + ABUF + i3 * ABUFSZ;

            // S = Q_hi K_hi^T (log2 domain)
            float sc[8][4] = {};
            #pragma unroll
            for (int ks = 0; ks < 4; ks++) {
                unsigned qh[4];
                unsigned qoff = ((w * 16 + (lane & 15)) * KSTR
                                 + ks * 16 + (lane >> 4) * 8) * 2;
                ldsm4(qh, sbase + AQH + qoff);
                #pragma unroll
                for (int np = 0; np < 4; np++) {
                    unsigned kh[4];
                    unsigned koff = ((np * 16 + (lane >> 4) * 8 + (lane & 7)) * KSTR
                                     + ks * 16 + ((lane >> 3) & 1) * 8) * 2;
                    ldsm4(kh, kvb + AKH + koff);
                    mma16(sc[2 * np],     qh, kh[0], kh[1]);
                    mma16(sc[2 * np + 1], qh, kh[2], kh[3]);
                }
            }

            // mask (diag ktile only)
            const bool diag = ((kt >> 1) == qt);
            if (diag) {
                #pragma unroll
                for (int ni = 0; ni < 8; ni++) {
                    int gk = kt * 64 + ni * 8 + 2 * quad;
                    if (!(causal ? (gk     <= gq0) : (gk     >= gq0))) sc[ni][0] = -1e30f;
                    if (!(causal ? (gk + 1 <= gq0) : (gk + 1 >= gq0))) sc[ni][1] = -1e30f;
                    if (!(causal ? (gk     <= gq1) : (gk     >= gq1))) sc[ni][2] = -1e30f;
                    if (!(causal ? (gk + 1 <= gq1) : (gk + 1 >= gq1))) sc[ni][3] = -1e30f;
                }
            }

            // online softmax (log2 domain)
            float mt0 = -1e30f, mt1 = -1e30f;
            #pragma unroll
            for (int ni = 0; ni < 8; ni++) {
                mt0 = fmaxf(mt0, fmaxf(sc[ni][0], sc[ni][1]));
                mt1 = fmaxf(mt1, fmaxf(sc[ni][2], sc[ni][3]));
            }
            mt0 = fmaxf(mt0, __shfl_xor_sync(0xffffffffu, mt0, 1));
            mt0 = fmaxf(mt0, __shfl_xor_sync(0xffffffffu, mt0, 2));
            mt1 = fmaxf(mt1, __shfl_xor_sync(0xffffffffu, mt1, 1));
            mt1 = fmaxf(mt1, __shfl_xor_sync(0xffffffffu, mt1, 2));

            float mn0 = fmaxf(m0, mt0), mn1 = fmaxf(m1, mt1);
            float cr0 = ex2(m0 - mn0), cr1 = ex2(m1 - mn1);
            m0 = mn0; m1 = mn1;

            float ls0 = 0.f, ls1 = 0.f;
            #pragma unroll
            for (int ni = 0; ni < 8; ni++) {
                sc[ni][0] = ex2(sc[ni][0] - mn0);
                sc[ni][1] = ex2(sc[ni][1] - mn0);
                sc[ni][2] = ex2(sc[ni][2] - mn1);
                sc[ni][3] = ex2(sc[ni][3] - mn1);
                ls0 += sc[ni][0] + sc[ni][1];
                ls1 += sc[ni][2] + sc[ni][3];
            }
            ls0 += __shfl_xor_sync(0xffffffffu, ls0, 1);
            ls0 += __shfl_xor_sync(0xffffffffu, ls0, 2);
            ls1 += __shfl_xor_sync(0xffffffffu, ls1, 1);
            ls1 += __shfl_xor_sync(0xffffffffu, ls1, 2);
            l0 = l0 * cr0 + ls0;
            l1 = l1 * cr1 + ls1;

            #pragma unroll
            for (int ni = 0; ni < 8; ni++) {
                o[ni][0] *= cr0; o[ni][1] *= cr0;
                o[ni][2] *= cr1; o[ni][3] *= cr1;
            }

            // PV: O += P_hi * V_hi
            #pragma unroll
            for (int ks = 0; ks < 4; ks++) {
                unsigned ph2[4];
                {
                    __half2 hh;
                    hh = __floats2half2_rn(sc[2*ks][0],   sc[2*ks][1]);
                    ph2[0] = *reinterpret_cast<unsigned*>(&hh);
                    hh = __floats2half2_rn(sc[2*ks][2],   sc[2*ks][3]);
                    ph2[1] = *reinterpret_cast<unsigned*>(&hh);
                    hh = __floats2half2_rn(sc[2*ks+1][0], sc[2*ks+1][1]);
                    ph2[2] = *reinterpret_cast<unsigned*>(&hh);
                    hh = __floats2half2_rn(sc[2*ks+1][2], sc[2*ks+1][3]);
                    ph2[3] = *reinterpret_cast<unsigned*>(&hh);
                }
                #pragma unroll
                for (int np = 0; np < 4; np++) {
                    unsigned vh[4];
                    unsigned voff = ((ks * 16 + (lane & 15)) * KSTR
                                     + np * 16 + (lane >> 4) * 8) * 2;
                    ldsm4t(vh, kvb + AVH + voff);
                    mma16(o[2 * np],     ph2, vh[0], vh[1]);
                    mma16(o[2 * np + 1], ph2, vh[2], vh[3]);
                }
            }
        }

        // write O as fp16 hi (flat (B,H,N,E))
        float inv0 = 1.f / l0, inv1 = 1.f / l1;
        const size_t ob = ((size_t)b * 16 + h) * NTOK * HDIM;
        #pragma unroll
        for (int ni = 0; ni < 8; ni++) {
            int c = ni * 8 + 2 * quad;
            __half2 h0 = __floats2half2_rn(o[ni][0] * inv0, o[ni][1] * inv0);
            __half2 h1 = __floats2half2_rn(o[ni][2] * inv1, o[ni][3] * inv1);
            size_t i0 = ob + (size_t)gq0 * HDIM + c;
            size_t i1 = ob + (size_t)gq1 * HDIM + c;
            *reinterpret_cast<__half2*>(&Oh[i0]) = h0;
            *reinterpret_cast<__half2*>(&Oh[i1]) = h1;
        }
    }
}

// ---------------------------------------------------------------------------
extern "C" void kernel_launch(void* const* d_in, const int* in_sizes, int n_in,
                              void* d_out, int out_size) {
    const float* x     = (const float*)d_in[0];
    const float* Wq_lb = (const float*)d_in[1];
    const float* Wk_lb = (const float*)d_in[2];
    const float* Wv_lb = (const float*)d_in[3];
    const float* Wq_la = (const float*)d_in[4];
    const float* Wk_la = (const float*)d_in[5];
    const float* Wv_la = (const float*)d_in[6];
    const float* Wo    = (const float*)d_in[7];

    __half *xh, *xl, *wh, *qkvh, *oh;
    cudaGetSymbolAddress((void**)&xh, g_xh);
    cudaGetSymbolAddress((void**)&xl, g_xl);
    cudaGetSymbolAddress((void**)&wh, g_wh);
    cudaGetSymbolAddress((void**)&qkvh, g_qkvh);
    cudaGetSymbolAddress((void**)&oh, g_oh);

    presplit<<<8192, 256>>>(x, Wq_lb, Wq_la, Wk_lb, Wk_la, Wv_lb, Wv_la, Wo,
                            xh, xl, wh);

    cudaFuncSetAttribute(gemm_hl<0>,
                         cudaFuncAttributeMaxDynamicSharedMemorySize, GEMMQ_SMEM);
    cudaFuncSetAttribute(gemm_hl<1>,
                         cudaFuncAttributeMaxDynamicSharedMemorySize, GEMM64_SMEM);
    cudaFuncSetAttribute(gemm_hl<2>,
                         cudaFuncAttributeMaxDynamicSharedMemorySize, GEMM64_SMEM);
    cudaFuncSetAttribute(attn_hl,
                         cudaFuncAttributeMaxDynamicSharedMemorySize, ATTN_SMEM);

    // KV projection (hi-only, BK64): cols 1024..3071
    gemm_hl<1><<<dim3(16, 32), 256, GEMM64_SMEM>>>(xh, nullptr, wh, qkvh, nullptr);
    // Q projection (hi+lo, BK32): cols 0..1023
    gemm_hl<0><<<dim3(8, 32), 256, GEMMQ_SMEM>>>(xh, xl, wh, qkvh, nullptr);
    // attention
    attn_hl<<<dim3(NTOK / 128, NHEAD / 2, BSZ), 256, ATTN_SMEM>>>(qkvh, oh);
    // output projection (hi-only, BK64)
    gemm_hl<2><<<dim3(8, 32), 256, GEMM64_SMEM>>>(oh, nullptr, wh, nullptr,
                                                  (float*)d_out);
}